// round 12
// baseline (speedup 1.0000x reference)
#include <cuda_runtime.h>
#include <cstdint>

#define NN 100000
#define NE 3200000
#define FIN 512
#define H   16
#define FOUT 128
#define NC  3

// ---------------- scratch (no allocations allowed) ----------------
__device__ float4 g_P1[NN * 4];    // layer-1 projected RAW (no norm), 16 f/node
__device__ float4 g_agg1[NN * 4];  // layer-1 aggregation target
__device__ float4 g_Q2[NN];        // (relu(...)*ns) @ Wc : 3 floats + pad per node
__device__ float4 g_agg2[NN];      // layer-2 aggregation target (3 floats + pad)
__device__ int    g_deg_out[NN];
__device__ int    g_deg_in[NN];
__device__ float  g_Wc[H * NC];    // W2 @ Wfc  (16x3)
__device__ float  g_bc[NC];        // b2 @ Wfc + bfc
__device__ int    g_is64;

// ---------------- f32x2 packed math helpers ----------------
typedef unsigned long long u64;

__device__ __forceinline__ u64 pack2(float a, float b) {
    u64 r; asm("mov.b64 %0, {%1, %2};" : "=l"(r) : "f"(a), "f"(b)); return r;
}
__device__ __forceinline__ void unpack2(u64 v, float& a, float& b) {
    asm("mov.b64 {%0, %1}, %2;" : "=f"(a), "=f"(b) : "l"(v));
}
__device__ __forceinline__ u64 fma2(u64 a, u64 b, u64 c) {
    u64 d; asm("fma.rn.f32x2 %0, %1, %2, %3;" : "=l"(d) : "l"(a), "l"(b), "l"(c)); return d;
}
__device__ __forceinline__ u64 add2(u64 a, u64 b) {
    u64 d; asm("add.rn.f32x2 %0, %1, %2;" : "=l"(d) : "l"(a), "l"(b)); return d;
}

__device__ __forceinline__ int eidx(const void* p, int e, int is64) {
    if (is64) return (int)__ldcs(((const long long*)p) + e);
    return __ldcs(((const int*)p) + e);
}

__device__ __forceinline__ void red_v4(float4* addr, float x, float y, float z, float w) {
    asm volatile("red.global.add.v4.f32 [%0], {%1, %2, %3, %4};"
                 :: "l"(addr), "f"(x), "f"(y), "f"(z), "f"(w) : "memory");
}

// merge a pair of partial accumulators across lanes differing in bit `off`:
// result corresponds to (pred ? b : a), summed over the lane pair.
__device__ __forceinline__ u64 mergepair(int pred, u64 a, u64 b, int off) {
    u64 keep = pred ? b : a;
    u64 send = pred ? a : b;
    return add2(keep, __shfl_xor_sync(0xffffffffu, send, off));
}

// ---------------- init 0: detect dtype + fused W2@Wfc (1 block) --------------
__global__ void k_init0(const unsigned* __restrict__ srcw,
                        const float* __restrict__ W2, const float* __restrict__ b2,
                        const float* __restrict__ Wfc, const float* __restrict__ bfc) {
    int t = threadIdx.x;
    if (t == 255) {  // int64 idx < 1e5 -> every odd 32-bit word is 0
        int is64 = 1;
        #pragma unroll 1
        for (int j = 0; j < 256; j++) {
            if (srcw[2 * j + 1] != 0u) { is64 = 0; break; }
        }
        g_is64 = is64;
    }
    if (t < H * NC) {
        int k = t / NC, c = t % NC;
        float s = 0.f;
        #pragma unroll 4
        for (int j = 0; j < FOUT; j++) s += W2[k * FOUT + j] * Wfc[j * NC + c];
        g_Wc[t] = s;
    }
    if (t >= 64 && t < 64 + NC) {
        int c = t - 64;
        float s = bfc[c];
        #pragma unroll 4
        for (int j = 0; j < FOUT; j++) s += b2[j] * Wfc[j * NC + c];
        g_bc[c] = s;
    }
}

// ---------------- init 1: zero degrees + agg2 --------------------------------
__global__ void k_init1() {
    int i = blockIdx.x * blockDim.x + threadIdx.x;
    if (i < NN) {
        g_deg_out[i] = 0;
        g_deg_in[i] = 0;
        g_agg2[i] = make_float4(0.f, 0.f, 0.f, 0.f);
    }
}

// ---------------- init 2: zero agg1 ------------------------------------------
__global__ void k_init2() {
    int i = blockIdx.x * blockDim.x + threadIdx.x;
    if (i < NN * 4) g_agg1[i] = make_float4(0.f, 0.f, 0.f, 0.f);
}

// ---------------- gemm1: K-half split + prefetch + migrating reduce ----------
// Pair blocks (2b, 2b+1) cover same 32 rows; khalf selects 8 of the 16 outputs.
// Warp = 4 rows, lane-split over features. NN % 32 == 0 -> no bounds checks.
__global__ void __launch_bounds__(256, 3) k_gemm1(const float* __restrict__ feat,
                                                  const float* __restrict__ W1) {
    __shared__ float2 Wp[4 * FIN];  // [kk_local][i]
    int khalf = blockIdx.x & 1;
    for (int t = threadIdx.x; t < FIN * 4; t += 256) {
        int i = t >> 2, kkl = t & 3;
        Wp[kkl * FIN + i] = ((const float2*)W1)[i * 8 + khalf * 4 + kkl];
    }
    __syncthreads();
    const u64* WpU = (const u64*)Wp;

    int warp = threadIdx.x >> 5, lane = threadIdx.x & 31;
    int row0 = ((blockIdx.x >> 1) * 8 + warp) * 4;
    const float* fp = feat + (size_t)row0 * FIN + lane;

    u64 acc[16];  // acc[4*r + q]
    #pragma unroll
    for (int k = 0; k < 16; k++) acc[k] = 0ull;

    float xc[4];
    #pragma unroll
    for (int r = 0; r < 4; r++) xc[r] = __ldg(fp + r * FIN);

    #pragma unroll
    for (int m = 0; m < 16; m++) {
        float xn[4];
        if (m < 15) {
            #pragma unroll
            for (int r = 0; r < 4; r++) xn[r] = __ldg(fp + r * FIN + 32 * (m + 1));
        }
        int i = lane + 32 * m;
        u64 wk[4];
        #pragma unroll
        for (int q = 0; q < 4; q++) wk[q] = WpU[q * FIN + i];
        #pragma unroll
        for (int r = 0; r < 4; r++) {
            u64 xx = pack2(xc[r], xc[r]);
            #pragma unroll
            for (int q = 0; q < 4; q++) acc[4 * r + q] = fma2(xx, wk[q], acc[4 * r + q]);
        }
        if (m < 15) {
            #pragma unroll
            for (int r = 0; r < 4; r++) xc[r] = xn[r];
        }
    }

    // migrating butterfly reduce: 16 -> 8 -> 4 -> 2 -> 1 values per lane.
    u64 B[8];
    #pragma unroll
    for (int j = 0; j < 8; j++) B[j] = mergepair(lane & 16, acc[2 * j], acc[2 * j + 1], 16);
    u64 C[4];
    #pragma unroll
    for (int j = 0; j < 4; j++) C[j] = mergepair(lane & 8, B[2 * j], B[2 * j + 1], 8);
    u64 D[2];
    #pragma unroll
    for (int j = 0; j < 2; j++) D[j] = mergepair(lane & 4, C[2 * j], C[2 * j + 1], 4);
    u64 E = mergepair(lane & 2, D[0], D[1], 2);
    E = add2(E, __shfl_xor_sync(0xffffffffu, E, 1));

    // lane (even) holds acc index idx = 8*b1 + 4*b2 + 2*b3 + b4
    if (!(lane & 1)) {
        int idx = (((lane >> 1) & 1) << 3) | (((lane >> 2) & 1) << 2)
                | (((lane >> 3) & 1) << 1) | ((lane >> 4) & 1);
        int r = idx >> 2, q = idx & 3;
        float a, b;
        unpack2(E, a, b);
        ((float2*)g_P1)[(size_t)(row0 + r) * 8 + khalf * 4 + q] = make_float2(a, b);
    }
}

// ---------------- degrees ----------------
__global__ void k_degree(const void* __restrict__ src, const void* __restrict__ dst) {
    int e = blockIdx.x * blockDim.x + threadIdx.x;
    if (e >= NE) return;
    int is64 = g_is64;
    atomicAdd(&g_deg_out[eidx(src, e, is64)], 1);
    atomicAdd(&g_deg_in[eidx(dst, e, is64)], 1);
}

// ---------------- scatter 1: agg1[dst] += ns[src] * P1[src] ------------------
__global__ void __launch_bounds__(256) k_scatter1(const void* __restrict__ src,
                                                  const void* __restrict__ dst) {
    int e = blockIdx.x * blockDim.x + threadIdx.x;
    if (e >= NE) return;
    int is64 = g_is64;
    int s = eidx(src, e, is64);
    int d = eidx(dst, e, is64);
    float ns = rsqrtf(fmaxf((float)__ldg(&g_deg_out[s]), 1.f));
    const float4* ps = (const float4*)g_P1 + s * 4;
    float4*       pd = g_agg1 + d * 4;
    #pragma unroll
    for (int c = 0; c < 4; c++) {
        float4 v = __ldg(ps + c);
        red_v4(pd + c, v.x * ns, v.y * ns, v.z * ns, v.w * ns);
    }
}

// ---------------- mid: Q2 = (relu(agg1*nd + b1)*ns) @ Wc ---------------------
__global__ void k_mid(const float* __restrict__ b1) {
    int n = blockIdx.x * blockDim.x + threadIdx.x;
    if (n >= NN) return;
    float nd = rsqrtf(fmaxf((float)g_deg_in[n], 1.f));
    float ns = rsqrtf(fmaxf((float)g_deg_out[n], 1.f));
    float o0 = 0.f, o1 = 0.f, o2 = 0.f;
    #pragma unroll
    for (int c = 0; c < 4; c++) {
        float4 a = g_agg1[n * 4 + c];
        float4 b = ((const float4*)b1)[c];
        float h0 = fmaxf(fmaf(a.x, nd, b.x), 0.f) * ns;
        float h1 = fmaxf(fmaf(a.y, nd, b.y), 0.f) * ns;
        float h2 = fmaxf(fmaf(a.z, nd, b.z), 0.f) * ns;
        float h3 = fmaxf(fmaf(a.w, nd, b.w), 0.f) * ns;
        int k = 4 * c;
        o0 = fmaf(h0, g_Wc[(k+0)*NC+0], fmaf(h1, g_Wc[(k+1)*NC+0],
             fmaf(h2, g_Wc[(k+2)*NC+0], fmaf(h3, g_Wc[(k+3)*NC+0], o0))));
        o1 = fmaf(h0, g_Wc[(k+0)*NC+1], fmaf(h1, g_Wc[(k+1)*NC+1],
             fmaf(h2, g_Wc[(k+2)*NC+1], fmaf(h3, g_Wc[(k+3)*NC+1], o1))));
        o2 = fmaf(h0, g_Wc[(k+0)*NC+2], fmaf(h1, g_Wc[(k+1)*NC+2],
             fmaf(h2, g_Wc[(k+2)*NC+2], fmaf(h3, g_Wc[(k+3)*NC+2], o2))));
    }
    g_Q2[n] = make_float4(o0, o1, o2, 0.f);
}

// ---------------- scatter 2: agg2[dst] += Q2[src]  (ONE v4 RED/edge) ---------
__global__ void __launch_bounds__(256) k_scatter2(const void* __restrict__ src,
                                                  const void* __restrict__ dst) {
    int e = blockIdx.x * blockDim.x + threadIdx.x;
    if (e >= NE) return;
    int is64 = g_is64;
    int s = eidx(src, e, is64);
    int d = eidx(dst, e, is64);
    float4 v = __ldg(g_Q2 + s);
    red_v4(g_agg2 + d, v.x, v.y, v.z, v.w);
}

// ---------------- final: out = nd * agg2 + bc -------------------------------
__global__ void k_final(float* __restrict__ out) {
    int n = blockIdx.x * blockDim.x + threadIdx.x;
    if (n >= NN) return;
    float nd = rsqrtf(fmaxf((float)g_deg_in[n], 1.f));
    float4 a = g_agg2[n];
    out[n * 3 + 0] = fmaf(a.x, nd, g_bc[0]);
    out[n * 3 + 1] = fmaf(a.y, nd, g_bc[1]);
    out[n * 3 + 2] = fmaf(a.z, nd, g_bc[2]);
}

// ---------------- launch ----------------
extern "C" void kernel_launch(void* const* d_in, const int* in_sizes, int n_in,
                              void* d_out, int out_size) {
    const float* features = (const float*)d_in[0];
    const void*  src      = d_in[1];
    const void*  dst      = d_in[2];
    const float* W1       = (const float*)d_in[3];
    const float* b1       = (const float*)d_in[4];
    const float* W2       = (const float*)d_in[5];
    const float* b2       = (const float*)d_in[6];
    const float* Wfc      = (const float*)d_in[7];
    const float* bfc      = (const float*)d_in[8];
    float* out = (float*)d_out;

    (void)in_sizes; (void)n_in; (void)out_size;

    const int EB = (NE + 255) / 256;
    const int NB = (NN + 255) / 256;
    const int GB = (NN / 32) * 2;  // paired k-half blocks

    k_init0<<<1, 256>>>((const unsigned*)src, W2, b2, Wfc, bfc);   // 1
    k_init1<<<NB, 256>>>();                                        // 2
    k_init2<<<(NN * 4 + 255) / 256, 256>>>();                      // 3
    k_gemm1<<<GB, 256>>>(features, W1);                            // 4 <- profiled
    k_degree<<<EB, 256>>>(src, dst);                               // 5
    k_scatter1<<<EB, 256>>>(src, dst);                             // 6
    k_mid<<<NB, 256>>>(b1);                                        // 7
    k_scatter2<<<EB, 256>>>(src, dst);                             // 8
    k_final<<<NB, 256>>>(out);                                     // 9
}

// round 15
// speedup vs baseline: 1.4909x; 1.4909x over previous
#include <cuda_runtime.h>
#include <cstdint>

#define NN 100000
#define NE 3200000
#define FIN 512
#define H   16
#define FOUT 128
#define NC  3

// ---------------- scratch (no allocations allowed) ----------------
__device__ float4 g_P1[NN * 4];    // layer-1 projected RAW (no norm), 16 f/node
__device__ float4 g_agg1[NN * 4];  // layer-1 aggregation target
__device__ float4 g_Q2[NN];        // (relu(...)*ns) @ Wc : 3 floats + pad per node
__device__ float4 g_agg2[NN];      // layer-2 aggregation target (3 floats + pad)
__device__ int    g_deg_out[NN];
__device__ int    g_deg_in[NN];
__device__ float  g_Wc[H * NC];    // W2 @ Wfc  (16x3)
__device__ float  g_bc[NC];        // b2 @ Wfc + bfc
__device__ int    g_is64;

// ---------------- f32x2 packed math helpers ----------------
typedef unsigned long long u64;

__device__ __forceinline__ u64 pack2(float a, float b) {
    u64 r; asm("mov.b64 %0, {%1, %2};" : "=l"(r) : "f"(a), "f"(b)); return r;
}
__device__ __forceinline__ void unpack2(u64 v, float& a, float& b) {
    asm("mov.b64 {%0, %1}, %2;" : "=f"(a), "=f"(b) : "l"(v));
}
__device__ __forceinline__ u64 fma2(u64 a, u64 b, u64 c) {
    u64 d; asm("fma.rn.f32x2 %0, %1, %2, %3;" : "=l"(d) : "l"(a), "l"(b), "l"(c)); return d;
}
__device__ __forceinline__ u64 add2(u64 a, u64 b) {
    u64 d; asm("add.rn.f32x2 %0, %1, %2;" : "=l"(d) : "l"(a), "l"(b)); return d;
}

__device__ __forceinline__ int eidx(const void* p, int e, int is64) {
    if (is64) return (int)__ldcs(((const long long*)p) + e);
    return __ldcs(((const int*)p) + e);
}

__device__ __forceinline__ void red_v4(float4* addr, float x, float y, float z, float w) {
    asm volatile("red.global.add.v4.f32 [%0], {%1, %2, %3, %4};"
                 :: "l"(addr), "f"(x), "f"(y), "f"(z), "f"(w) : "memory");
}

// merge a pair of partial accumulators across lanes differing in bit `off`
__device__ __forceinline__ u64 mergepair(int pred, u64 a, u64 b, int off) {
    u64 keep = pred ? b : a;
    u64 send = pred ? a : b;
    return add2(keep, __shfl_xor_sync(0xffffffffu, send, off));
}

// ---------------- init 0: detect dtype + fused W2@Wfc (1 block) --------------
__global__ void k_init0(const unsigned* __restrict__ srcw,
                        const float* __restrict__ W2, const float* __restrict__ b2,
                        const float* __restrict__ Wfc, const float* __restrict__ bfc) {
    int t = threadIdx.x;
    if (t == 255) {  // int64 idx < 1e5 -> every odd 32-bit word is 0
        int is64 = 1;
        #pragma unroll 1
        for (int j = 0; j < 256; j++) {
            if (srcw[2 * j + 1] != 0u) { is64 = 0; break; }
        }
        g_is64 = is64;
    }
    if (t < H * NC) {
        int k = t / NC, c = t % NC;
        float s = 0.f;
        #pragma unroll 4
        for (int j = 0; j < FOUT; j++) s += W2[k * FOUT + j] * Wfc[j * NC + c];
        g_Wc[t] = s;
    }
    if (t >= 64 && t < 64 + NC) {
        int c = t - 64;
        float s = bfc[c];
        #pragma unroll 4
        for (int j = 0; j < FOUT; j++) s += b2[j] * Wfc[j * NC + c];
        g_bc[c] = s;
    }
}

// ---------------- init 1: zero degrees + agg2 --------------------------------
__global__ void k_init1() {
    int i = blockIdx.x * blockDim.x + threadIdx.x;
    if (i < NN) {
        g_deg_out[i] = 0;
        g_deg_in[i] = 0;
        g_agg2[i] = make_float4(0.f, 0.f, 0.f, 0.f);
    }
}

// ---------------- init 2: zero agg1 ------------------------------------------
__global__ void k_init2() {
    int i = blockIdx.x * blockDim.x + threadIdx.x;
    if (i < NN * 4) g_agg1[i] = make_float4(0.f, 0.f, 0.f, 0.f);
}

// ---------------- FAT v2: gemm (k-half, vectorized) + degree roles -----------
#define GEMM_B ((NN / 32) * 2)      // 6250 gemm blocks (paired k-halves)
#define EDGE_B ((NE + 255) / 256)   // 12500 degree blocks

__global__ void __launch_bounds__(256, 3) k_fat(const float* __restrict__ feat,
                                                const float* __restrict__ W1,
                                                const void* __restrict__ src,
                                                const void* __restrict__ dst) {
    if (blockIdx.x >= GEMM_B) {
        // -------- degree role --------
        int e = (blockIdx.x - GEMM_B) * blockDim.x + threadIdx.x;
        if (e >= NE) return;
        int is64 = g_is64;
        atomicAdd(&g_deg_out[eidx(src, e, is64)], 1);
        atomicAdd(&g_deg_in[eidx(dst, e, is64)], 1);
        return;
    }

    // -------- gemm role: P1[:, khalf*8 .. khalf*8+8) = feat @ W1 -------------
    __shared__ float2 Wp[4 * FIN];  // [q][i] weight pairs for this k-half
    int khalf = blockIdx.x & 1;
    for (int t = threadIdx.x; t < FIN * 4; t += 256) {
        int i = t >> 2, q = t & 3;
        Wp[q * FIN + i] = ((const float2*)W1)[i * 8 + khalf * 4 + q];
    }
    __syncthreads();
    const ulonglong2* Wv = (const ulonglong2*)Wp;  // [q][i/2] pairs of u64

    int warp = threadIdx.x >> 5, lane = threadIdx.x & 31;
    int row0 = ((blockIdx.x >> 1) * 8 + warp) * 4;
    const float2* fp = (const float2*)(feat + (size_t)row0 * FIN) + lane;

    u64 acc[16];  // acc[4*r + q]
    #pragma unroll
    for (int k = 0; k < 16; k++) acc[k] = 0ull;

    float2 xc[4];
    #pragma unroll
    for (int r = 0; r < 4; r++) xc[r] = __ldg(fp + r * (FIN / 2));

    #pragma unroll
    for (int m = 0; m < 8; m++) {
        float2 xn[4];
        if (m < 7) {
            #pragma unroll
            for (int r = 0; r < 4; r++) xn[r] = __ldg(fp + r * (FIN / 2) + 32 * (m + 1));
        }
        int iv = lane + 32 * m;  // ulonglong2 index within a q-row (FIN/2 = 256)
        ulonglong2 wk[4];
        #pragma unroll
        for (int q = 0; q < 4; q++) wk[q] = Wv[q * (FIN / 2) + iv];
        #pragma unroll
        for (int r = 0; r < 4; r++) {
            u64 xx0 = pack2(xc[r].x, xc[r].x);
            u64 xx1 = pack2(xc[r].y, xc[r].y);
            #pragma unroll
            for (int q = 0; q < 4; q++) {
                acc[4 * r + q] = fma2(xx0, wk[q].x, acc[4 * r + q]);
                acc[4 * r + q] = fma2(xx1, wk[q].y, acc[4 * r + q]);
            }
        }
        if (m < 7) {
            #pragma unroll
            for (int r = 0; r < 4; r++) xc[r] = xn[r];
        }
    }

    // migrating butterfly reduce: 16 -> 8 -> 4 -> 2 -> 1 values per lane.
    u64 B[8];
    #pragma unroll
    for (int j = 0; j < 8; j++) B[j] = mergepair(lane & 16, acc[2 * j], acc[2 * j + 1], 16);
    u64 C[4];
    #pragma unroll
    for (int j = 0; j < 4; j++) C[j] = mergepair(lane & 8, B[2 * j], B[2 * j + 1], 8);
    u64 D[2];
    #pragma unroll
    for (int j = 0; j < 2; j++) D[j] = mergepair(lane & 4, C[2 * j], C[2 * j + 1], 4);
    u64 E = mergepair(lane & 2, D[0], D[1], 2);
    E = add2(E, __shfl_xor_sync(0xffffffffu, E, 1));

    if (!(lane & 1)) {
        int idx = (((lane >> 1) & 1) << 3) | (((lane >> 2) & 1) << 2)
                | (((lane >> 3) & 1) << 1) | ((lane >> 4) & 1);
        int r = idx >> 2, q = idx & 3;
        float a, b;
        unpack2(E, a, b);
        ((float2*)g_P1)[(size_t)(row0 + r) * 8 + khalf * 4 + q] = make_float2(a, b);
    }
}

// ---------------- scatter 1: agg1[dst] += ns[src] * P1[src] ------------------
__global__ void __launch_bounds__(256) k_scatter1(const void* __restrict__ src,
                                                  const void* __restrict__ dst) {
    int e = blockIdx.x * blockDim.x + threadIdx.x;
    if (e >= NE) return;
    int is64 = g_is64;
    int s = eidx(src, e, is64);
    int d = eidx(dst, e, is64);
    float ns = rsqrtf(fmaxf((float)__ldg(&g_deg_out[s]), 1.f));
    const float4* ps = (const float4*)g_P1 + s * 4;
    float4*       pd = g_agg1 + d * 4;
    #pragma unroll
    for (int c = 0; c < 4; c++) {
        float4 v = __ldg(ps + c);
        red_v4(pd + c, v.x * ns, v.y * ns, v.z * ns, v.w * ns);
    }
}

// ---------------- mid: Q2 = (relu(agg1*nd + b1)*ns) @ Wc ---------------------
__global__ void k_mid(const float* __restrict__ b1) {
    int n = blockIdx.x * blockDim.x + threadIdx.x;
    if (n >= NN) return;
    float nd = rsqrtf(fmaxf((float)g_deg_in[n], 1.f));
    float ns = rsqrtf(fmaxf((float)g_deg_out[n], 1.f));
    float o0 = 0.f, o1 = 0.f, o2 = 0.f;
    #pragma unroll
    for (int c = 0; c < 4; c++) {
        float4 a = g_agg1[n * 4 + c];
        float4 b = ((const float4*)b1)[c];
        float h0 = fmaxf(fmaf(a.x, nd, b.x), 0.f) * ns;
        float h1 = fmaxf(fmaf(a.y, nd, b.y), 0.f) * ns;
        float h2 = fmaxf(fmaf(a.z, nd, b.z), 0.f) * ns;
        float h3 = fmaxf(fmaf(a.w, nd, b.w), 0.f) * ns;
        int k = 4 * c;
        o0 = fmaf(h0, g_Wc[(k+0)*NC+0], fmaf(h1, g_Wc[(k+1)*NC+0],
             fmaf(h2, g_Wc[(k+2)*NC+0], fmaf(h3, g_Wc[(k+3)*NC+0], o0))));
        o1 = fmaf(h0, g_Wc[(k+0)*NC+1], fmaf(h1, g_Wc[(k+1)*NC+1],
             fmaf(h2, g_Wc[(k+2)*NC+1], fmaf(h3, g_Wc[(k+3)*NC+1], o1))));
        o2 = fmaf(h0, g_Wc[(k+0)*NC+2], fmaf(h1, g_Wc[(k+1)*NC+2],
             fmaf(h2, g_Wc[(k+2)*NC+2], fmaf(h3, g_Wc[(k+3)*NC+2], o2))));
    }
    g_Q2[n] = make_float4(o0, o1, o2, 0.f);
}

// ---------------- scatter 2: agg2[dst] += Q2[src]  (ONE v4 RED/edge) ---------
__global__ void __launch_bounds__(256) k_scatter2(const void* __restrict__ src,
                                                  const void* __restrict__ dst) {
    int e = blockIdx.x * blockDim.x + threadIdx.x;
    if (e >= NE) return;
    int is64 = g_is64;
    int s = eidx(src, e, is64);
    int d = eidx(dst, e, is64);
    float4 v = __ldg(g_Q2 + s);
    red_v4(g_agg2 + d, v.x, v.y, v.z, v.w);
}

// ---------------- final: out = nd * agg2 + bc -------------------------------
__global__ void k_final(float* __restrict__ out) {
    int n = blockIdx.x * blockDim.x + threadIdx.x;
    if (n >= NN) return;
    float nd = rsqrtf(fmaxf((float)g_deg_in[n], 1.f));
    float4 a = g_agg2[n];
    out[n * 3 + 0] = fmaf(a.x, nd, g_bc[0]);
    out[n * 3 + 1] = fmaf(a.y, nd, g_bc[1]);
    out[n * 3 + 2] = fmaf(a.z, nd, g_bc[2]);
}

// ---------------- launch ----------------
extern "C" void kernel_launch(void* const* d_in, const int* in_sizes, int n_in,
                              void* d_out, int out_size) {
    const float* features = (const float*)d_in[0];
    const void*  src      = d_in[1];
    const void*  dst      = d_in[2];
    const float* W1       = (const float*)d_in[3];
    const float* b1       = (const float*)d_in[4];
    const float* W2       = (const float*)d_in[5];
    const float* b2       = (const float*)d_in[6];
    const float* Wfc      = (const float*)d_in[7];
    const float* bfc      = (const float*)d_in[8];
    float* out = (float*)d_out;

    (void)in_sizes; (void)n_in; (void)out_size;

    const int EB = EDGE_B;
    const int NB = (NN + 255) / 256;

    k_init0<<<1, 256>>>((const unsigned*)src, W2, b2, Wfc, bfc);   // 1
    k_init1<<<NB, 256>>>();                                        // 2
    k_init2<<<(NN * 4 + 255) / 256, 256>>>();                      // 3
    k_fat<<<GEMM_B + EDGE_B, 256>>>(features, W1, src, dst);       // 4 <- profiled
    k_scatter1<<<EB, 256>>>(src, dst);                             // 5
    k_mid<<<NB, 256>>>(b1);                                        // 6
    k_scatter2<<<EB, 256>>>(src, dst);                             // 7
    k_final<<<NB, 256>>>(out);                                     // 8
}